// round 3
// baseline (speedup 1.0000x reference)
#include <cuda_runtime.h>

// AttentionalPropagation: x [B=64, C=512, L=4096] fp32.
// Per l: q = x[:,:,l] (64x512); S = q q^T / sqrt(C); P = softmax(S); msg = P q;
// out = x + msg.
//
// R2 changes vs R1 baseline (1888us):
//  - fp32x2 packed FMA (fma.rn.f32x2) in both GEMM passes: halves FMA-pipe
//    instruction count (sm_103a dual-issue fp32 pipe).
//  - Double-buffered smem staging in both passes: chunk ch+1's global loads
//    are issued before computing chunk ch, hiding DRAM latency + STS drain
//    behind compute instead of serializing at each barrier.

namespace {

constexpr int kB  = 64;
constexpr int kC  = 512;
constexpr int kL  = 4096;
constexpr int LT  = 8;            // l-positions per CTA (8 x 4B = 32B sectors)
constexpr int CCH = 32;           // c per chunk
constexpr int NCH = kC / CCH;     // 16 chunks
constexpr int NT  = 512;          // threads per CTA

constexpr int P1_BUF = CCH * LT * kB;   // 16384 floats per pass-1 buffer

constexpr int XS2_PB = 33;              // pass-2 x buffer pitch over b (pad)
constexpr int XS2_PL = kB * XS2_PB;     // 2112 floats per l
constexpr int MB_P   = 259;             // msg transpose pitch (259%32=3, coprime)

// Pass-2 owns the high-water mark: 2 x-chunk buffers + mb.
constexpr int SMEM_FLOATS = 2 * LT * XS2_PL + kB * MB_P;  // 33792 + 16576 = 50368
constexpr int SMEM_BYTES  = SMEM_FLOATS * 4;              // 201472 B (< 227 KB)
static_assert(2 * P1_BUF <= 2 * LT * XS2_PL, "pass1 buffers fit in pass2 region");

typedef unsigned long long u64;

__device__ __forceinline__ u64 pk(float lo, float hi) {
    u64 r; asm("mov.b64 %0, {%1,%2};" : "=l"(r) : "f"(lo), "f"(hi)); return r;
}
__device__ __forceinline__ void upk(u64 v, float& lo, float& hi) {
    asm("mov.b64 {%0,%1}, %2;" : "=f"(lo), "=f"(hi) : "l"(v));
}
__device__ __forceinline__ u64 ffma2(u64 a, u64 b, u64 c) {
    u64 d; asm("fma.rn.f32x2 %0, %1, %2, %3;" : "=l"(d) : "l"(a), "l"(b), "l"(c));
    return d;
}

// Stage one c-chunk of x into pass-1 layout [cc][lt][b] (b fastest).
__device__ __forceinline__ void load_p1(const float* __restrict__ x, float* buf,
                                        int c0, int l0, int t) {
    #pragma unroll
    for (int k = 0; k < (kB * CCH) / NT; k++) {
        const int r  = t + k * NT;
        const int cl = r >> 6;
        const int b  = r & 63;
        const float* gp = x + ((size_t)(b * kC + (c0 + cl)) * kL + l0);
        const float4 v0 = *(const float4*)gp;
        const float4 v1 = *(const float4*)(gp + 4);
        float* sp = buf + cl * (LT * kB) + b;
        sp[0 * kB] = v0.x; sp[1 * kB] = v0.y; sp[2 * kB] = v0.z; sp[3 * kB] = v0.w;
        sp[4 * kB] = v1.x; sp[5 * kB] = v1.y; sp[6 * kB] = v1.z; sp[7 * kB] = v1.w;
    }
}

// Stage one c-chunk of x into pass-2 layout [lt][b][XS2_PB].
__device__ __forceinline__ void load_p2(const float* __restrict__ x, float* buf,
                                        int c0, int l0, int t) {
    #pragma unroll
    for (int k = 0; k < (kB * CCH) / NT; k++) {
        const int r  = t + k * NT;
        const int cl = r >> 6;
        const int b  = r & 63;
        const float* gp = x + ((size_t)(b * kC + (c0 + cl)) * kL + l0);
        const float4 v0 = *(const float4*)gp;
        const float4 v1 = *(const float4*)(gp + 4);
        float* sp = buf + b * XS2_PB + cl;
        sp[0 * XS2_PL] = v0.x; sp[1 * XS2_PL] = v0.y; sp[2 * XS2_PL] = v0.z; sp[3 * XS2_PL] = v0.w;
        sp[4 * XS2_PL] = v1.x; sp[5 * XS2_PL] = v1.y; sp[6 * XS2_PL] = v1.z; sp[7 * XS2_PL] = v1.w;
    }
}

__global__ void __launch_bounds__(NT, 1)
attn_prop_kernel(const float* __restrict__ x, float* __restrict__ out) {
    extern __shared__ float sm[];
    float* mb = sm + 2 * LT * XS2_PL;   // msg transpose buffer

    const int t  = threadIdx.x;
    const int l0 = blockIdx.x * LT;
    const int g  = t >> 6;           // l within tile (0..7)
    const int u  = t & 63;
    const int tn = u >> 3;           // n-tile (rows n = tn*8..+7)
    const int tm = u & 7;            // m-tile (cols m = tm*8..+7)

    // acc2[i][jj] = packed pair (S[i][2jj], S[i][2jj+1]) of the 8x8 tile.
    u64 acc2[8][4];
    #pragma unroll
    for (int i = 0; i < 8; i++)
        #pragma unroll
        for (int jj = 0; jj < 4; jj++) acc2[i][jj] = pk(0.0f, 0.0f);

    // ------------------------------ Pass 1: S = q q^T ------------------------
    load_p1(x, sm, 0, l0, t);
    __syncthreads();
    for (int ch = 0; ch < NCH; ch++) {
        if (ch + 1 < NCH)
            load_p1(x, sm + ((ch + 1) & 1) * P1_BUF, (ch + 1) * CCH, l0, t);
        const float* buf = sm + (ch & 1) * P1_BUF;
        #pragma unroll 2
        for (int cc = 0; cc < CCH; cc++) {
            const float* base = buf + cc * (LT * kB) + g * kB;
            const float4 a0 = *(const float4*)(base + tn * 8);
            const float4 a1 = *(const float4*)(base + tn * 8 + 4);
            const float4 b0 = *(const float4*)(base + tm * 8);
            const float4 b1 = *(const float4*)(base + tm * 8 + 4);
            const u64 qb2[4] = {pk(b0.x, b0.y), pk(b0.z, b0.w),
                                pk(b1.x, b1.y), pk(b1.z, b1.w)};
            const float qa[8] = {a0.x, a0.y, a0.z, a0.w, a1.x, a1.y, a1.z, a1.w};
            #pragma unroll
            for (int i = 0; i < 8; i++) {
                const u64 qa2 = pk(qa[i], qa[i]);
                #pragma unroll
                for (int jj = 0; jj < 4; jj++)
                    acc2[i][jj] = ffma2(qa2, qb2[jj], acc2[i][jj]);
            }
        }
        __syncthreads();
    }

    // ------------------------------ Softmax (registers + 8-lane shfl) --------
    const float inv_scale = 0.044194173824159216f;  // 1/sqrt(512)
    #pragma unroll
    for (int i = 0; i < 8; i++) {
        float v[8];
        #pragma unroll
        for (int jj = 0; jj < 4; jj++) upk(acc2[i][jj], v[2 * jj], v[2 * jj + 1]);
        float mx = -1e30f;
        #pragma unroll
        for (int j = 0; j < 8; j++) { v[j] *= inv_scale; mx = fmaxf(mx, v[j]); }
        mx = fmaxf(mx, __shfl_xor_sync(0xffffffffu, mx, 1));
        mx = fmaxf(mx, __shfl_xor_sync(0xffffffffu, mx, 2));
        mx = fmaxf(mx, __shfl_xor_sync(0xffffffffu, mx, 4));
        float s = 0.0f;
        #pragma unroll
        for (int j = 0; j < 8; j++) { v[j] = __expf(v[j] - mx); s += v[j]; }
        s += __shfl_xor_sync(0xffffffffu, s, 1);
        s += __shfl_xor_sync(0xffffffffu, s, 2);
        s += __shfl_xor_sync(0xffffffffu, s, 4);
        const float inv = 1.0f / s;
        #pragma unroll
        for (int j = 0; j < 8; j++) v[j] *= inv;
        #pragma unroll
        for (int jj = 0; jj < 4; jj++) acc2[i][jj] = pk(v[2 * jj], v[2 * jj + 1]);
    }

    // ------------------------------ Pass 2: out = x + P q --------------------
    load_p2(x, sm, 0, l0, t);   // prologue (pass-1 smem fully drained by loop-end sync)
    __syncthreads();
    for (int ch = 0; ch < NCH; ch++) {
        const int c0 = ch * CCH;
        if (ch + 1 < NCH)
            load_p2(x, sm + ((ch + 1) & 1) * (LT * XS2_PL), (ch + 1) * CCH, l0, t);
        const float* xbuf = sm + (ch & 1) * (LT * XS2_PL);

        // msg[n][c] = sum_m P[n][m] q[m][c]; each thread sums its 8 m's with
        // packed pairs, then 8-lane shfl reduction over tm.
        #pragma unroll 2
        for (int cc = 0; cc < CCH; cc++) {
            const float* qp = xbuf + g * XS2_PL + (tm * 8) * XS2_PB + cc;
            float qv[8];
            #pragma unroll
            for (int j = 0; j < 8; j++) qv[j] = qp[j * XS2_PB];
            const u64 qv2[4] = {pk(qv[0], qv[1]), pk(qv[2], qv[3]),
                                pk(qv[4], qv[5]), pk(qv[6], qv[7])};
            float part[8];
            #pragma unroll
            for (int i = 0; i < 8; i++) {
                u64 p2 = ffma2(acc2[i][0], qv2[0], pk(0.0f, 0.0f));
                p2 = ffma2(acc2[i][1], qv2[1], p2);
                p2 = ffma2(acc2[i][2], qv2[2], p2);
                p2 = ffma2(acc2[i][3], qv2[3], p2);
                float lo, hi; upk(p2, lo, hi);
                part[i] = lo + hi;
            }
            #pragma unroll
            for (int i = 0; i < 8; i++) {
                part[i] += __shfl_xor_sync(0xffffffffu, part[i], 1);
                part[i] += __shfl_xor_sync(0xffffffffu, part[i], 2);
                part[i] += __shfl_xor_sync(0xffffffffu, part[i], 4);
            }
            float myv = part[0];
            #pragma unroll
            for (int i = 1; i < 8; i++) if (tm == i) myv = part[i];
            mb[u * MB_P + cc * 8 + g] = myv;
        }
        __syncthreads();

        // out = x + msg, coalesced 32B sectors.
        #pragma unroll
        for (int k = 0; k < (kB * CCH) / NT; k++) {
            const int r  = t + k * NT;
            const int cl = r >> 6;
            const int b  = r & 63;
            const float* mp = mb   + b * MB_P  + cl * 8;
            const float* xp = xbuf + b * XS2_PB + cl;
            float4 o0, o1;
            o0.x = xp[0 * XS2_PL] + mp[0];
            o0.y = xp[1 * XS2_PL] + mp[1];
            o0.z = xp[2 * XS2_PL] + mp[2];
            o0.w = xp[3 * XS2_PL] + mp[3];
            o1.x = xp[4 * XS2_PL] + mp[4];
            o1.y = xp[5 * XS2_PL] + mp[5];
            o1.z = xp[6 * XS2_PL] + mp[6];
            o1.w = xp[7 * XS2_PL] + mp[7];
            float* gp = out + ((size_t)(b * kC + (c0 + cl)) * kL + l0);
            *(float4*)gp       = o0;
            *(float4*)(gp + 4) = o1;
        }
        __syncthreads();   // mb + xbuf drained before next chunk reuses them
    }
}

}  // namespace

extern "C" void kernel_launch(void* const* d_in, const int* in_sizes, int n_in,
                              void* d_out, int out_size) {
    (void)in_sizes; (void)n_in; (void)out_size;
    const float* x = (const float*)d_in[0];
    float* out     = (float*)d_out;

    cudaFuncSetAttribute(attn_prop_kernel,
                         cudaFuncAttributeMaxDynamicSharedMemorySize, SMEM_BYTES);

    attn_prop_kernel<<<kL / LT, NT, SMEM_BYTES>>>(x, out);
}

// round 4
// speedup vs baseline: 1.0458x; 1.0458x over previous
#include <cuda_runtime.h>
#include <cstdint>

// AttentionalPropagation via warp-level tf32 tensor cores (mma.sync.m16n8k8).
// x [B=64, C=512, L=4096] fp32. Per l: q = x[:,:,l]; S = q q^T / sqrt(C);
// P = softmax(S); out = x + P q.
//
// R3: replaces the fp32 SIMT GEMM (ceiling ~960us) with tf32 mma.sync.
//  - CTA = 4 l's x 4 warps each. Warp (l, strip) computes 16 full rows of S
//    -> softmax is warp-local in mma accumulator fragments.
//  - P stored tf32-rounded in smem (pitch 68 -> conflict-free A-frag loads).
//  - x streamed in c-chunks of 32 through double-buffered smem laid out
//    [b][c][l] (pitch 134: 2-way worst-case LDS conflicts, 16B l-groups).
//    LDG(next) -> mma(cur) -> STS(next) order hides DRAM latency behind mma.
//  - Pass-1 staging stores cvt.rna tf32 values (operands only); pass-2
//    staging stays exact fp32 for the residual, B-frags cvt in-register.
//  - msg staged through smem so out stores are float4 over l.

namespace {

constexpr int kB  = 64;
constexpr int kC  = 512;
constexpr int kL  = 4096;
constexpr int LT  = 4;              // l's per CTA
constexpr int CCH = 32;             // c per chunk
constexpr int NCH = kC / CCH;       // 16
constexpr int NT  = 512;            // 16 warps

constexpr int XP   = 134;           // staging pitch per b (floats): cc*4 + l + pad
constexpr int XBUF = kB * XP;       // 8576 floats per chunk buffer
constexpr int PP   = 68;            // P pitch per row (4*r0+q4 = lane -> conflict-free)
constexpr int PL   = kB * PP;       // 4352 floats per l

constexpr int SM_X0 = 0;
constexpr int SM_X1 = XBUF;
constexpr int SM_P  = 2 * XBUF;             // 17152
constexpr int SM_M  = SM_P + LT * PL;       // 17152 + 17408 = 34560
constexpr int SMEM_FLOATS = SM_M + XBUF;    // 43136
constexpr int SMEM_BYTES  = SMEM_FLOATS * 4;  // 172544 B

__device__ __forceinline__ uint32_t f2tf(float f) {
    uint32_t u; asm("cvt.rna.tf32.f32 %0, %1;" : "=r"(u) : "f"(f)); return u;
}
__device__ __forceinline__ uint32_t fbits(float f) { return __float_as_uint(f); }

__device__ __forceinline__ void mma_tf32(float d[4],
                                         uint32_t a0, uint32_t a1, uint32_t a2, uint32_t a3,
                                         uint32_t b0, uint32_t b1) {
    asm volatile(
        "mma.sync.aligned.m16n8k8.row.col.f32.tf32.tf32.f32 "
        "{%0,%1,%2,%3}, {%4,%5,%6,%7}, {%8,%9}, {%0,%1,%2,%3};"
        : "+f"(d[0]), "+f"(d[1]), "+f"(d[2]), "+f"(d[3])
        : "r"(a0), "r"(a1), "r"(a2), "r"(a3), "r"(b0), "r"(b1));
}

__global__ void __launch_bounds__(NT, 1)
attn_tc_kernel(const float* __restrict__ x, float* __restrict__ out) {
    extern __shared__ float sm[];
    float* Pbuf = sm + SM_P;
    float* Mbuf = sm + SM_M;

    const int t     = threadIdx.x;
    const int lane  = t & 31;
    const int w     = t >> 5;
    const int l     = w & 3;          // l within CTA tile
    const int strip = w >> 2;         // 16-row strip of the 64-row output
    const int l0    = blockIdx.x * LT;
    const int r0    = lane >> 2;      // mma groupID (0..7)
    const int q4    = lane & 3;       // thread-in-group (0..3)

    // Per-thread staging ownership: idx = t + k*NT -> b = idx&63, cc = idx>>6.
    const int sb  = t & 63;           // b for staging (cc = (t>>6) + 8k)
    const int sc0 = t >> 6;

    // ============================ Pass 1: S = q q^T =========================
    float acc[8][4];
    #pragma unroll
    for (int j = 0; j < 8; j++)
        #pragma unroll
        for (int i = 0; i < 4; i++) acc[j][i] = 0.0f;

    float4 ld[4];
    #pragma unroll
    for (int k = 0; k < 4; k++)
        ld[k] = *(const float4*)(x + ((size_t)(sb * kC + (sc0 + 8 * k))) * kL + l0);
    #pragma unroll
    for (int k = 0; k < 4; k++) {
        float* sp = sm + SM_X0 + sb * XP + (sc0 + 8 * k) * 4;
        sp[0] = __uint_as_float(f2tf(ld[k].x));
        sp[1] = __uint_as_float(f2tf(ld[k].y));
        sp[2] = __uint_as_float(f2tf(ld[k].z));
        sp[3] = __uint_as_float(f2tf(ld[k].w));
    }
    __syncthreads();

    #pragma unroll 1
    for (int ch = 0; ch < NCH; ch++) {
        if (ch + 1 < NCH) {
            const int c0n = (ch + 1) * CCH;
            #pragma unroll
            for (int k = 0; k < 4; k++)
                ld[k] = *(const float4*)(x + ((size_t)(sb * kC + (c0n + sc0 + 8 * k))) * kL + l0);
        }
        const float* buf = sm + ((ch & 1) ? SM_X1 : SM_X0);
        #pragma unroll
        for (int s = 0; s < 4; s++) {
            const float* ab = buf + (strip * 16 + r0) * XP + (8 * s + q4) * 4 + l;
            const uint32_t a0 = fbits(ab[0]);
            const uint32_t a1 = fbits(ab[8 * XP]);
            const uint32_t a2 = fbits(ab[16]);
            const uint32_t a3 = fbits(ab[8 * XP + 16]);
            #pragma unroll
            for (int j = 0; j < 8; j++) {
                const float* bb = buf + (8 * j + r0) * XP + (8 * s + q4) * 4 + l;
                mma_tf32(acc[j], a0, a1, a2, a3, fbits(bb[0]), fbits(bb[16]));
            }
        }
        if (ch + 1 < NCH) {
            float* nb = sm + (((ch + 1) & 1) ? SM_X1 : SM_X0);
            #pragma unroll
            for (int k = 0; k < 4; k++) {
                float* sp = nb + sb * XP + (sc0 + 8 * k) * 4;
                sp[0] = __uint_as_float(f2tf(ld[k].x));
                sp[1] = __uint_as_float(f2tf(ld[k].y));
                sp[2] = __uint_as_float(f2tf(ld[k].z));
                sp[3] = __uint_as_float(f2tf(ld[k].w));
            }
        }
        __syncthreads();
    }

    // ====================== Softmax (warp-local, 2 rows/thread) =============
    {
        const float isc = 0.044194173824159216f;   // 1/sqrt(512)
        float m0 = -1e30f, m1 = -1e30f;
        #pragma unroll
        for (int j = 0; j < 8; j++) {
            #pragma unroll
            for (int i = 0; i < 4; i++) acc[j][i] *= isc;
            m0 = fmaxf(m0, fmaxf(acc[j][0], acc[j][1]));
            m1 = fmaxf(m1, fmaxf(acc[j][2], acc[j][3]));
        }
        m0 = fmaxf(m0, __shfl_xor_sync(0xffffffffu, m0, 1));
        m0 = fmaxf(m0, __shfl_xor_sync(0xffffffffu, m0, 2));
        m1 = fmaxf(m1, __shfl_xor_sync(0xffffffffu, m1, 1));
        m1 = fmaxf(m1, __shfl_xor_sync(0xffffffffu, m1, 2));
        float s0 = 0.0f, s1 = 0.0f;
        #pragma unroll
        for (int j = 0; j < 8; j++) {
            acc[j][0] = __expf(acc[j][0] - m0); s0 += acc[j][0];
            acc[j][1] = __expf(acc[j][1] - m0); s0 += acc[j][1];
            acc[j][2] = __expf(acc[j][2] - m1); s1 += acc[j][2];
            acc[j][3] = __expf(acc[j][3] - m1); s1 += acc[j][3];
        }
        s0 += __shfl_xor_sync(0xffffffffu, s0, 1);
        s0 += __shfl_xor_sync(0xffffffffu, s0, 2);
        s1 += __shfl_xor_sync(0xffffffffu, s1, 1);
        s1 += __shfl_xor_sync(0xffffffffu, s1, 2);
        const float i0 = 1.0f / s0, i1 = 1.0f / s1;
        float* pb = Pbuf + l * PL;
        const int n0 = strip * 16 + r0;
        #pragma unroll
        for (int j = 0; j < 8; j++) {
            const int mcol = 8 * j + 2 * q4;
            pb[n0 * PP + mcol]           = __uint_as_float(f2tf(acc[j][0] * i0));
            pb[n0 * PP + mcol + 1]       = __uint_as_float(f2tf(acc[j][1] * i0));
            pb[(n0 + 8) * PP + mcol]     = __uint_as_float(f2tf(acc[j][2] * i1));
            pb[(n0 + 8) * PP + mcol + 1] = __uint_as_float(f2tf(acc[j][3] * i1));
        }
    }

    // ============================ Pass 2: out = x + P q =====================
    #pragma unroll
    for (int k = 0; k < 4; k++)
        ld[k] = *(const float4*)(x + ((size_t)(sb * kC + (sc0 + 8 * k))) * kL + l0);
    #pragma unroll
    for (int k = 0; k < 4; k++) {
        float* sp = sm + SM_X0 + sb * XP + (sc0 + 8 * k) * 4;
        sp[0] = ld[k].x; sp[1] = ld[k].y; sp[2] = ld[k].z; sp[3] = ld[k].w;
    }
    __syncthreads();   // covers P writes + chunk-0 staging

    const float* pb = Pbuf + l * PL;
    #pragma unroll 1
    for (int ch = 0; ch < NCH; ch++) {
        if (ch + 1 < NCH) {
            const int c0n = (ch + 1) * CCH;
            #pragma unroll
            for (int k = 0; k < 4; k++)
                ld[k] = *(const float4*)(x + ((size_t)(sb * kC + (c0n + sc0 + 8 * k))) * kL + l0);
        }
        const float* buf = sm + ((ch & 1) ? SM_X1 : SM_X0);

        float macc[4][4];
        #pragma unroll
        for (int j2 = 0; j2 < 4; j2++)
            #pragma unroll
            for (int i = 0; i < 4; i++) macc[j2][i] = 0.0f;

        #pragma unroll
        for (int s = 0; s < 8; s++) {   // k-steps over m = 64
            const float* ab = pb + (strip * 16 + r0) * PP + 8 * s + q4;
            const uint32_t a0 = fbits(ab[0]);
            const uint32_t a1 = fbits(ab[8 * PP]);
            const uint32_t a2 = fbits(ab[4]);
            const uint32_t a3 = fbits(ab[8 * PP + 4]);
            #pragma unroll
            for (int j2 = 0; j2 < 4; j2++) {
                const float* bb = buf + (8 * s + q4) * XP + (8 * j2 + r0) * 4 + l;
                mma_tf32(macc[j2], a0, a1, a2, a3, f2tf(bb[0]), f2tf(bb[4 * XP]));
            }
        }

        // msg -> smem [b(=n)][cc][l]
        {
            float* mb = Mbuf + (strip * 16 + r0) * XP + l;
            #pragma unroll
            for (int j2 = 0; j2 < 4; j2++) {
                const int co = (8 * j2 + 2 * q4) * 4;
                mb[co]              = macc[j2][0];
                mb[co + 4]          = macc[j2][1];
                mb[8 * XP + co]     = macc[j2][2];
                mb[8 * XP + co + 4] = macc[j2][3];
            }
        }
        __syncthreads();

        // out = x + msg (float4 over l), then stage next chunk.
        {
            const int c0 = ch * CCH;
            #pragma unroll
            for (int k = 0; k < 4; k++) {
                const int cc = sc0 + 8 * k;
                const float* mp = Mbuf + sb * XP + cc * 4;
                const float* xp = buf  + sb * XP + cc * 4;
                const float2 ma = *(const float2*)mp;
                const float2 mc = *(const float2*)(mp + 2);
                const float2 xa = *(const float2*)xp;
                const float2 xc = *(const float2*)(xp + 2);
                float4 o;
                o.x = xa.x + ma.x; o.y = xa.y + ma.y;
                o.z = xc.x + mc.x; o.w = xc.y + mc.y;
                *(float4*)(out + ((size_t)(sb * kC + (c0 + cc))) * kL + l0) = o;
            }
        }
        if (ch + 1 < NCH) {
            float* nb = sm + (((ch + 1) & 1) ? SM_X1 : SM_X0);
            #pragma unroll
            for (int k = 0; k < 4; k++) {
                float* sp = nb + sb * XP + (sc0 + 8 * k) * 4;
                sp[0] = ld[k].x; sp[1] = ld[k].y; sp[2] = ld[k].z; sp[3] = ld[k].w;
            }
        }
        __syncthreads();
    }
}

}  // namespace

extern "C" void kernel_launch(void* const* d_in, const int* in_sizes, int n_in,
                              void* d_out, int out_size) {
    (void)in_sizes; (void)n_in; (void)out_size;
    const float* x = (const float*)d_in[0];
    float* out     = (float*)d_out;

    cudaFuncSetAttribute(attn_tc_kernel,
                         cudaFuncAttributeMaxDynamicSharedMemorySize, SMEM_BYTES);

    attn_tc_kernel<<<kL / LT, NT, SMEM_BYTES>>>(x, out);
}

// round 5
// speedup vs baseline: 1.4030x; 1.3415x over previous
#include <cuda_runtime.h>
#include <cstdint>

// AttentionalPropagation via tf32 mma.sync, R4 redesign.
// x [B=64, C=512, L=4096] fp32. Per l: q = x[:,:,l]; S = q q^T / sqrt(C);
// P = softmax(S); out = x + P q.
//
//  - CTA = 8 l's x 2 warps each (NT=512, grid 512). Warp owns 32 full rows of
//    its l's 64x64 score matrix -> softmax warp-local.
//  - P lives in registers: pass-1 accumulator fragments are permuted in-place
//    into pass-2 A-fragments with one-time shfls (no P smem, no P reloads).
//  - x streamed in c-chunks of 32 via cp.async (8B granules) into an
//    XOR-swizzled smem layout (pitch 258 words/b; l-granule ^= c&3) that is
//    <=2-way bank-conflicted for every mma fragment access pattern.
//  - One wait_group+barrier per pass-1 chunk; pass-2 adds one barrier for the
//    msg transpose buffer so stores are full 32B sectors.
//  - tf32 mma consumes raw fp32 bits (hw truncates low mantissa): rel_err~2e-4.

namespace {

constexpr int kB  = 64;
constexpr int kC  = 512;
constexpr int kL  = 4096;
constexpr int LT  = 8;             // l per CTA
constexpr int CCH = 32;            // c per chunk
constexpr int NCH = kC / CCH;      // 16
constexpr int NT  = 512;           // 16 warps = 2 per l

constexpr int PB   = CCH * 8 + 2;  // 258 words per b-row in staging (2-word pad)
constexpr int XBUF = kB * PB;      // 16512 words per staging buffer
constexpr int PM   = CCH * 8 + 4;  // 260 words per n-row in msg (16B-aligned rows)
constexpr int SMEM_WORDS = 2 * XBUF + kB * PM;   // 33024 + 16640 = 49664
constexpr int SMEM_BYTES = SMEM_WORDS * 4;       // 198656 B (< 227 KB)

__device__ __forceinline__ uint32_t fbits(float f) { return __float_as_uint(f); }

__device__ __forceinline__ void cp8(uint32_t dst, const void* src) {
    asm volatile("cp.async.ca.shared.global [%0], [%1], 8;" :: "r"(dst), "l"(src));
}
__device__ __forceinline__ void cp_commit() {
    asm volatile("cp.async.commit_group;" ::: "memory");
}
__device__ __forceinline__ void cp_wait0() {
    asm volatile("cp.async.wait_group 0;" ::: "memory");
}

__device__ __forceinline__ void mma_tf32(float d[4],
                                         uint32_t a0, uint32_t a1, uint32_t a2, uint32_t a3,
                                         uint32_t b0, uint32_t b1) {
    asm volatile(
        "mma.sync.aligned.m16n8k8.row.col.f32.tf32.tf32.f32 "
        "{%0,%1,%2,%3}, {%4,%5,%6,%7}, {%8,%9}, {%0,%1,%2,%3};"
        : "+f"(d[0]), "+f"(d[1]), "+f"(d[2]), "+f"(d[3])
        : "r"(a0), "r"(a1), "r"(a2), "r"(a3), "r"(b0), "r"(b1));
}

// Stage one c-chunk: word(b,c,g) = b*PB + c*8 + ((g ^ (c&3))<<1), g = l>>1.
__device__ __forceinline__ void stage(const float* __restrict__ x, uint32_t sbase,
                                      int c0, int l0, int t) {
    #pragma unroll
    for (int k = 0; k < 4; k++) {
        const int idx = t + k * NT;
        const int b = idx & 63;
        const int c = idx >> 6;
        const float* src = x + ((size_t)(b * kC + (c0 + c)) * kL + l0);
        const uint32_t drow = sbase + (uint32_t)(b * PB + c * 8) * 4u;
        const int cx = c & 3;
        #pragma unroll
        for (int g = 0; g < 4; g++)
            cp8(drow + (uint32_t)(((g ^ cx) << 1) * 4), src + 2 * g);
    }
}

__global__ void __launch_bounds__(NT, 1)
attn_tc2_kernel(const float* __restrict__ x, float* __restrict__ out) {
    extern __shared__ float sm[];
    float* msg = sm + 2 * XBUF;

    const int t     = threadIdx.x;
    const int lane  = t & 31;
    const int w     = t >> 5;
    const int l     = w >> 1;        // l within CTA (0..7)
    const int strip = w & 1;         // 32-row half of the 64x64 matrix
    const int l0    = blockIdx.x * LT;
    const int r0    = lane >> 2;     // mma groupID
    const int q4    = lane & 3;      // thread-in-group
    const int lg    = l >> 1;        // l granule (2 floats)
    const int lb    = l & 1;
    const uint32_t smbase = (uint32_t)__cvta_generic_to_shared(sm);

    // acc[b2][j][i]: S[strip*32 + b2*16 + r0 + 8*(i>>1)][8j + 2q4 + (i&1)]
    float acc[2][8][4];
    #pragma unroll
    for (int b2 = 0; b2 < 2; b2++)
        #pragma unroll
        for (int j = 0; j < 8; j++)
            #pragma unroll
            for (int i = 0; i < 4; i++) acc[b2][j][i] = 0.0f;

    // ============================ Pass 1: S = q q^T =========================
    stage(x, smbase, 0, l0, t);
    cp_commit();

    #pragma unroll 1
    for (int ch = 0; ch < NCH; ch++) {
        cp_wait0();
        __syncthreads();   // chunk ch staged everywhere; prior compute done
        if (ch + 1 < NCH) {
            stage(x, smbase + (uint32_t)(((ch + 1) & 1) * XBUF) * 4u,
                  (ch + 1) * CCH, l0, t);
            cp_commit();
        }
        const float* buf = sm + (ch & 1) * XBUF;
        #pragma unroll
        for (int s = 0; s < 4; s++) {
            const int ccol = 8 * s + q4;
            const int xr   = ((lg ^ q4) << 1) + lb;   // (ccol&3)==q4, (ccol+4)&3==q4
            uint32_t a[2][4];
            #pragma unroll
            for (int b2 = 0; b2 < 2; b2++) {
                const float* ap = buf + (strip * 32 + b2 * 16 + r0) * PB + ccol * 8 + xr;
                a[b2][0] = fbits(ap[0]);
                a[b2][1] = fbits(ap[8 * PB]);
                a[b2][2] = fbits(ap[32]);
                a[b2][3] = fbits(ap[8 * PB + 32]);
            }
            #pragma unroll
            for (int j = 0; j < 8; j++) {
                const float* bp = buf + (8 * j + r0) * PB + ccol * 8 + xr;
                const uint32_t b0 = fbits(bp[0]);
                const uint32_t b1 = fbits(bp[32]);
                mma_tf32(acc[0][j], a[0][0], a[0][1], a[0][2], a[0][3], b0, b1);
                mma_tf32(acc[1][j], a[1][0], a[1][1], a[1][2], a[1][3], b0, b1);
            }
        }
    }

    // Pass-2 chunk-0 prefetch overlaps the softmax below (buf0 free: its last
    // readers finished before the final pass-1 barrier).
    stage(x, smbase, 0, l0, t);
    cp_commit();

    // ====================== Softmax (warp-local, 4 rows/thread) =============
    {
        const float isc = 0.044194173824159216f;   // 1/sqrt(512)
        #pragma unroll
        for (int b2 = 0; b2 < 2; b2++) {
            #pragma unroll
            for (int h = 0; h < 2; h++) {
                float mx = -1e30f;
                #pragma unroll
                for (int j = 0; j < 8; j++) {
                    acc[b2][j][2 * h]     *= isc;
                    acc[b2][j][2 * h + 1] *= isc;
                    mx = fmaxf(mx, fmaxf(acc[b2][j][2 * h], acc[b2][j][2 * h + 1]));
                }
                mx = fmaxf(mx, __shfl_xor_sync(0xffffffffu, mx, 1));
                mx = fmaxf(mx, __shfl_xor_sync(0xffffffffu, mx, 2));
                float ssum = 0.0f;
                #pragma unroll
                for (int j = 0; j < 8; j++) {
                    const float e0 = __expf(acc[b2][j][2 * h] - mx);
                    const float e1 = __expf(acc[b2][j][2 * h + 1] - mx);
                    acc[b2][j][2 * h] = e0; acc[b2][j][2 * h + 1] = e1;
                    ssum += e0 + e1;
                }
                ssum += __shfl_xor_sync(0xffffffffu, ssum, 1);
                ssum += __shfl_xor_sync(0xffffffffu, ssum, 2);
                const float inv = 1.0f / ssum;
                #pragma unroll
                for (int j = 0; j < 8; j++) {
                    acc[b2][j][2 * h] *= inv; acc[b2][j][2 * h + 1] *= inv;
                }
            }
        }
    }

    // ===== Convert P accumulator frags -> A frags in place (shfl permute) ===
    // Target (b2,s): a0 = P[r0][8s+q4]   a1 = P[r0+8][8s+q4]
    //                a2 = P[r0][8s+q4+4] a3 = P[r0+8][8s+q4+4]
    // Source: acc[b2][s][p / 2+p] of lanes (r0, q4>>1) and (r0, (q4>>1)+2).
    {
        const int srcA = (lane & 28) | (q4 >> 1);
        const int srcB = srcA | 2;
        const bool odd = (q4 & 1) != 0;
        #pragma unroll
        for (int b2 = 0; b2 < 2; b2++) {
            #pragma unroll
            for (int s = 0; s < 8; s++) {
                const float v0 = __shfl_sync(0xffffffffu, acc[b2][s][0], srcA);
                const float v1 = __shfl_sync(0xffffffffu, acc[b2][s][1], srcA);
                const float v2 = __shfl_sync(0xffffffffu, acc[b2][s][2], srcA);
                const float v3 = __shfl_sync(0xffffffffu, acc[b2][s][3], srcA);
                const float w0 = __shfl_sync(0xffffffffu, acc[b2][s][0], srcB);
                const float w1 = __shfl_sync(0xffffffffu, acc[b2][s][1], srcB);
                const float w2 = __shfl_sync(0xffffffffu, acc[b2][s][2], srcB);
                const float w3 = __shfl_sync(0xffffffffu, acc[b2][s][3], srcB);
                acc[b2][s][0] = odd ? v1 : v0;   // acc now holds A-frags of P
                acc[b2][s][1] = odd ? v3 : v2;
                acc[b2][s][2] = odd ? w1 : w0;
                acc[b2][s][3] = odd ? w3 : w2;
            }
        }
    }

    // ============================ Pass 2: out = x + P q =====================
    #pragma unroll 1
    for (int ch = 0; ch < NCH; ch++) {
        cp_wait0();
        __syncthreads();   // chunk ch staged; prior epilogue done with msg+buf
        if (ch + 1 < NCH) {
            stage(x, smbase + (uint32_t)(((ch + 1) & 1) * XBUF) * 4u,
                  (ch + 1) * CCH, l0, t);
            cp_commit();
        }
        const float* buf = sm + (ch & 1) * XBUF;

        float macc[2][4][4];
        #pragma unroll
        for (int b2 = 0; b2 < 2; b2++)
            #pragma unroll
            for (int j2 = 0; j2 < 4; j2++)
                #pragma unroll
                for (int i = 0; i < 4; i++) macc[b2][j2][i] = 0.0f;

        #pragma unroll
        for (int s = 0; s < 8; s++) {       // k-steps over m = 64
            #pragma unroll
            for (int j2 = 0; j2 < 4; j2++) {
                const int cb = 8 * j2 + r0;
                const float* bp = buf + (8 * s + q4) * PB + cb * 8
                                  + ((lg ^ (cb & 3)) << 1) + lb;
                const uint32_t b0 = fbits(bp[0]);
                const uint32_t b1 = fbits(bp[4 * PB]);
                mma_tf32(macc[0][j2], fbits(acc[0][s][0]), fbits(acc[0][s][1]),
                         fbits(acc[0][s][2]), fbits(acc[0][s][3]), b0, b1);
                mma_tf32(macc[1][j2], fbits(acc[1][s][0]), fbits(acc[1][s][1]),
                         fbits(acc[1][s][2]), fbits(acc[1][s][3]), b0, b1);
            }
        }

        // msg fragments -> smem transpose buffer [n][c][l] (pitch PM)
        #pragma unroll
        for (int b2 = 0; b2 < 2; b2++) {
            #pragma unroll
            for (int j2 = 0; j2 < 4; j2++) {
                const int n = strip * 32 + b2 * 16 + r0;
                const int c = 8 * j2 + 2 * q4;
                msg[n * PM + c * 8 + l]           = macc[b2][j2][0];
                msg[n * PM + (c + 1) * 8 + l]     = macc[b2][j2][1];
                msg[(n + 8) * PM + c * 8 + l]     = macc[b2][j2][2];
                msg[(n + 8) * PM + (c + 1) * 8 + l] = macc[b2][j2][3];
            }
        }
        __syncthreads();

        // Epilogue: out = x + msg, full 32B-sector stores.
        const int c0 = ch * CCH;
        #pragma unroll
        for (int k = 0; k < 4; k++) {
            const int idx = t + k * NT;
            const int b = idx & 63;
            const int c = idx >> 6;
            const int cx = c & 3;
            float xl[8];
            const float* xb = buf + b * PB + c * 8;
            #pragma unroll
            for (int g = 0; g < 4; g++) {
                const float2 v = *(const float2*)(xb + ((g ^ cx) << 1));
                xl[2 * g] = v.x; xl[2 * g + 1] = v.y;
            }
            const float* mp = msg + b * PM + c * 8;
            const float4 m0 = *(const float4*)mp;
            const float4 m1 = *(const float4*)(mp + 4);
            float* op = out + ((size_t)(b * kC + (c0 + c)) * kL + l0);
            float4 o0, o1;
            o0.x = xl[0] + m0.x; o0.y = xl[1] + m0.y;
            o0.z = xl[2] + m0.z; o0.w = xl[3] + m0.w;
            o1.x = xl[4] + m1.x; o1.y = xl[5] + m1.y;
            o1.z = xl[6] + m1.z; o1.w = xl[7] + m1.w;
            *(float4*)op       = o0;
            *(float4*)(op + 4) = o1;
        }
    }
}

}  // namespace

extern "C" void kernel_launch(void* const* d_in, const int* in_sizes, int n_in,
                              void* d_out, int out_size) {
    (void)in_sizes; (void)n_in; (void)out_size;
    const float* x = (const float*)d_in[0];
    float* out     = (float*)d_out;

    cudaFuncSetAttribute(attn_tc2_kernel,
                         cudaFuncAttributeMaxDynamicSharedMemorySize, SMEM_BYTES);

    attn_tc2_kernel<<<kL / LT, NT, SMEM_BYTES>>>(x, out);
}